// round 1
// baseline (speedup 1.0000x reference)
#include <cuda_runtime.h>
#include <cuda_bf16.h>
#include <math.h>

// Problem constants
#define NUM_O   5000
#define NUM_T   20000
#define DD      128
#define HH      512
#define GG      64
#define LL      5
// derived
#define K1      (3*DD)        // 384
#define N2      (2*HH+DD)     // 1152

// ---------------- scratch (__device__ globals; allocation-free) ----------------
__device__ float g_ov    [NUM_O * DD];          // object vectors (ping target of GEMM4)
__device__ float g_t     [NUM_T * K1];          // concat(ov[s], pv, ov[o])
__device__ float g_h     [NUM_T * HH];          // hidden of net1
__device__ float g_nt    [NUM_T * N2];          // new_t (s | p | o)
__device__ float g_pooled[NUM_O * HH];
__device__ float g_h2    [NUM_O * HH];
__device__ float g_counts[NUM_O];
__device__ float g_invcnt[NUM_O];
__device__ float g_scores[NUM_O];
__device__ float g_gvec  [GG * DD];

// ---------------- tiny kernels ----------------
__global__ void zero_kernel(float* p, int n) {
    int i = blockIdx.x * blockDim.x + threadIdx.x;
    if (i < n) p[i] = 0.f;
}

__global__ void gather_ov_init(const float* __restrict__ obj_emb,
                               const int* __restrict__ objs,
                               float* __restrict__ ov) {
    int i = blockIdx.x, d = threadIdx.x;
    ov[i * DD + d] = obj_emb[objs[i] * DD + d];
}

__global__ void count_kernel(const int* __restrict__ trip, float* __restrict__ counts) {
    int i = blockIdx.x * blockDim.x + threadIdx.x;
    if (i < NUM_T) {
        atomicAdd(&counts[trip[3 * i + 0]], 1.f);
        atomicAdd(&counts[trip[3 * i + 2]], 1.f);
    }
}

__global__ void inv_kernel(const float* __restrict__ counts, float* __restrict__ inv) {
    int i = blockIdx.x * blockDim.x + threadIdx.x;
    if (i < NUM_O) inv[i] = 1.f / fmaxf(counts[i], 1.f);
}

// t[i] = [ov[s], pv, ov[o]]; pv from pred_emb (layer 0) or g_nt[:,512:640]
__global__ void build_t(const float* __restrict__ ov,
                        const float* __restrict__ pred_emb,
                        const float* __restrict__ nt,
                        const int* __restrict__ trip,
                        float* __restrict__ t, int use_emb) {
    int i = blockIdx.x, d = threadIdx.x;
    int s = trip[3 * i + 0];
    int p = trip[3 * i + 1];
    int o = trip[3 * i + 2];
    float pvv = use_emb ? pred_emb[p * DD + d]
                        : nt[(size_t)i * N2 + HH + d];
    size_t base = (size_t)i * K1;
    t[base + d]           = ov[s * DD + d];
    t[base + DD + d]      = pvv;
    t[base + 2 * DD + d]  = ov[o * DD + d];
}

// scatter-add: pooled[s] += nt[:, :512]; pooled[o] += nt[:, 640:1152]
__global__ void scatter_kernel(const int* __restrict__ trip,
                               const float* __restrict__ nt,
                               float* __restrict__ pooled) {
    int i = blockIdx.x;
    int j = threadIdx.x;            // 0..255
    const float* base = nt + (size_t)i * N2;
    if (j < 128) {                  // subject slice, cols [0,512)
        int s = trip[3 * i + 0];
        float4 v = *reinterpret_cast<const float4*>(base + j * 4);
        float* dst = pooled + (size_t)s * HH + j * 4;
        atomicAdd(dst + 0, v.x); atomicAdd(dst + 1, v.y);
        atomicAdd(dst + 2, v.z); atomicAdd(dst + 3, v.w);
    } else {                        // object slice, cols [640,1152)
        int jo = j - 128;
        int o = trip[3 * i + 2];
        float4 v = *reinterpret_cast<const float4*>(base + HH + DD + jo * 4);
        float* dst = pooled + (size_t)o * HH + jo * 4;
        atomicAdd(dst + 0, v.x); atomicAdd(dst + 1, v.y);
        atomicAdd(dst + 2, v.z); atomicAdd(dst + 3, v.w);
    }
}

__global__ void scale_rows(float* __restrict__ pooled, const float* __restrict__ inv, int n) {
    int i = blockIdx.x * blockDim.x + threadIdx.x;
    if (i < n) pooled[i] *= inv[i >> 9];   // 512 cols
}

// ---------------- SGEMM, C = relu(A@B + bias) ----------------
// A: MxK row-major, B: KxN row-major, bias: N. N%128==0, K%8==0 guaranteed.
#define BM 128
#define BN 128
#define BK 8

__global__ void __launch_bounds__(256)
sgemm_bias_relu(const float* __restrict__ A, const float* __restrict__ B,
                const float* __restrict__ bias, float* __restrict__ C,
                int M, int N, int K) {
    __shared__ float As[BK][BM];
    __shared__ float Bs[BK][BN];

    int bm = blockIdx.y * BM;
    int bn = blockIdx.x * BN;
    int tid = threadIdx.x;
    int tx = tid & 15, ty = tid >> 4;

    int a_row = tid >> 1;           // 0..127
    int a_col = (tid & 1) * 4;      // 0 or 4
    int b_k   = tid >> 5;           // 0..7
    int b_n   = (tid & 31) * 4;     // 0..124

    float acc[8][8] = {};
    float ra[8], rb[8];

    for (int k0 = 0; k0 < K; k0 += BK) {
        // load A tile (transposed into smem), guard M
        {
            int gr = bm + a_row;
            float4 v = make_float4(0.f, 0.f, 0.f, 0.f);
            if (gr < M)
                v = *reinterpret_cast<const float4*>(A + (size_t)gr * K + k0 + a_col);
            As[a_col + 0][a_row] = v.x;
            As[a_col + 1][a_row] = v.y;
            As[a_col + 2][a_row] = v.z;
            As[a_col + 3][a_row] = v.w;
        }
        // load B tile
        {
            float4 v = *reinterpret_cast<const float4*>(
                B + (size_t)(k0 + b_k) * N + bn + b_n);
            *reinterpret_cast<float4*>(&Bs[b_k][b_n]) = v;
        }
        __syncthreads();
#pragma unroll
        for (int k = 0; k < BK; k++) {
#pragma unroll
            for (int i = 0; i < 8; i++) ra[i] = As[k][ty * 8 + i];
#pragma unroll
            for (int j = 0; j < 8; j++) rb[j] = Bs[k][tx * 8 + j];
#pragma unroll
            for (int i = 0; i < 8; i++)
#pragma unroll
                for (int j = 0; j < 8; j++)
                    acc[i][j] += ra[i] * rb[j];
        }
        __syncthreads();
    }

#pragma unroll
    for (int i = 0; i < 8; i++) {
        int gr = bm + ty * 8 + i;
        if (gr >= M) continue;
#pragma unroll
        for (int j = 0; j < 8; j += 4) {
            int gc = bn + tx * 8 + j;
            float4 v;
            v.x = fmaxf(acc[i][j + 0] + bias[gc + 0], 0.f);
            v.y = fmaxf(acc[i][j + 1] + bias[gc + 1], 0.f);
            v.z = fmaxf(acc[i][j + 2] + bias[gc + 2], 0.f);
            v.w = fmaxf(acc[i][j + 3] + bias[gc + 3], 0.f);
            *reinterpret_cast<float4*>(C + (size_t)gr * N + gc) = v;
        }
    }
}

// ---------------- attention epilogue ----------------
__global__ void scores_kernel(const float* __restrict__ ov,
                              const float* __restrict__ att_w,
                              const float* __restrict__ att_b,
                              float* __restrict__ scores) {
    int gid = blockIdx.x * blockDim.x + threadIdx.x;
    int w = gid >> 5, lane = gid & 31;
    if (w >= NUM_O) return;
    float sum = 0.f;
#pragma unroll
    for (int d = lane; d < DD; d += 32) sum += ov[(size_t)w * DD + d] * att_w[d];
#pragma unroll
    for (int off = 16; off; off >>= 1) sum += __shfl_down_sync(0xffffffff, sum, off);
    if (lane == 0) scores[w] = sum + att_b[0];
}

// one block per image: segment max/softmax/weighted-sum (obj_to_img is sorted)
__global__ void segment_kernel(const float* __restrict__ scores,
                               const int* __restrict__ img,
                               const float* __restrict__ ov,
                               float* __restrict__ gvec) {
    int g = blockIdx.x, t = threadIdx.x;   // 128 threads
    __shared__ float sred[128];
    __shared__ int ired[128];

    float m = -3.4e38f;
    int lo = NUM_O, hi = -1;
    for (int i = t; i < NUM_O; i += 128) {
        if (img[i] == g) {
            m = fmaxf(m, scores[i]);
            lo = min(lo, i);
            hi = max(hi, i);
        }
    }
    sred[t] = m; __syncthreads();
    for (int s = 64; s > 0; s >>= 1) { if (t < s) sred[t] = fmaxf(sred[t], sred[t + s]); __syncthreads(); }
    m = sred[0]; __syncthreads();
    ired[t] = lo; __syncthreads();
    for (int s = 64; s > 0; s >>= 1) { if (t < s) ired[t] = min(ired[t], ired[t + s]); __syncthreads(); }
    lo = ired[0]; __syncthreads();
    ired[t] = hi; __syncthreads();
    for (int s = 64; s > 0; s >>= 1) { if (t < s) ired[t] = max(ired[t], ired[t + s]); __syncthreads(); }
    hi = ired[0]; __syncthreads();

    float z = 0.f;
    for (int i = lo + t; i <= hi; i += 128)
        if (img[i] == g) z += expf(scores[i] - m);
    sred[t] = z; __syncthreads();
    for (int s = 64; s > 0; s >>= 1) { if (t < s) sred[t] += sred[t + s]; __syncthreads(); }
    z = sred[0];
    float invz = 1.f / z;

    float acc = 0.f;
    for (int i = lo; i <= hi; i++) {
        if (img[i] == g)
            acc += expf(scores[i] - m) * invz * ov[(size_t)i * DD + t];
    }
    gvec[g * DD + t] = acc;
}

__global__ void concat_kernel(const float* __restrict__ ov,
                              const float* __restrict__ gvec,
                              const int* __restrict__ img,
                              float* __restrict__ out) {
    int i = blockIdx.x, t = threadIdx.x;   // 256 threads
    if (t < DD) out[(size_t)i * 256 + t] = ov[(size_t)i * DD + t];
    else        out[(size_t)i * 256 + t] = gvec[img[i] * DD + (t - DD)];
}

// ---------------- launch ----------------
extern "C" void kernel_launch(void* const* d_in, const int* in_sizes, int n_in,
                              void* d_out, int out_size) {
    const int*   objs     = (const int*)d_in[0];
    const int*   trip     = (const int*)d_in[1];
    const int*   img      = (const int*)d_in[2];
    const float* obj_emb  = (const float*)d_in[3];
    const float* pred_emb = (const float*)d_in[4];
    const float* n1w1     = (const float*)d_in[5];
    const float* n1b1     = (const float*)d_in[6];
    const float* n1w2     = (const float*)d_in[7];
    const float* n1b2     = (const float*)d_in[8];
    const float* n2w1     = (const float*)d_in[9];
    const float* n2b1     = (const float*)d_in[10];
    const float* n2w2     = (const float*)d_in[11];
    const float* n2b2     = (const float*)d_in[12];
    const float* att_w    = (const float*)d_in[13];
    const float* att_b    = (const float*)d_in[14];
    float* out = (float*)d_out;

    float *ov, *t, *h, *nt, *pooled, *h2, *counts, *inv, *scores, *gvec;
    cudaGetSymbolAddress((void**)&ov,     g_ov);
    cudaGetSymbolAddress((void**)&t,      g_t);
    cudaGetSymbolAddress((void**)&h,      g_h);
    cudaGetSymbolAddress((void**)&nt,     g_nt);
    cudaGetSymbolAddress((void**)&pooled, g_pooled);
    cudaGetSymbolAddress((void**)&h2,     g_h2);
    cudaGetSymbolAddress((void**)&counts, g_counts);
    cudaGetSymbolAddress((void**)&inv,    g_invcnt);
    cudaGetSymbolAddress((void**)&scores, g_scores);
    cudaGetSymbolAddress((void**)&gvec,   g_gvec);

    gather_ov_init<<<NUM_O, DD>>>(obj_emb, objs, ov);
    zero_kernel<<<(NUM_O + 255) / 256, 256>>>(counts, NUM_O);
    count_kernel<<<(NUM_T + 255) / 256, 256>>>(trip, counts);
    inv_kernel<<<(NUM_O + 255) / 256, 256>>>(counts, inv);

    const int mT  = (NUM_T + BM - 1) / BM;   // 157
    const int mO  = (NUM_O + BM - 1) / BM;   // 40

    for (int l = 0; l < LL; l++) {
        build_t<<<NUM_T, DD>>>(ov, pred_emb, nt, trip, t, l == 0 ? 1 : 0);

        sgemm_bias_relu<<<dim3(HH / BN, mT), 256>>>(
            t, n1w1 + (size_t)l * K1 * HH, n1b1 + (size_t)l * HH, h,
            NUM_T, HH, K1);

        sgemm_bias_relu<<<dim3(N2 / BN, mT), 256>>>(
            h, n1w2 + (size_t)l * HH * N2, n1b2 + (size_t)l * N2, nt,
            NUM_T, N2, HH);

        zero_kernel<<<(NUM_O * HH + 255) / 256, 256>>>(pooled, NUM_O * HH);
        scatter_kernel<<<NUM_T, 256>>>(trip, nt, pooled);
        scale_rows<<<(NUM_O * HH + 255) / 256, 256>>>(pooled, inv, NUM_O * HH);

        sgemm_bias_relu<<<dim3(HH / BN, mO), 256>>>(
            pooled, n2w1 + (size_t)l * HH * HH, n2b1 + (size_t)l * HH, h2,
            NUM_O, HH, HH);

        sgemm_bias_relu<<<dim3(DD / BN, mO), 256>>>(
            h2, n2w2 + (size_t)l * HH * DD, n2b2 + (size_t)l * DD, ov,
            NUM_O, DD, HH);
    }

    scores_kernel<<<(NUM_O * 32 + 255) / 256, 256>>>(ov, att_w, att_b, scores);
    segment_kernel<<<GG, 128>>>(scores, img, ov, gvec);
    concat_kernel<<<NUM_O, 256>>>(ov, gvec, img, out);
}

// round 3
// speedup vs baseline: 2.3592x; 2.3592x over previous
#include <cuda_runtime.h>
#include <cuda_bf16.h>
#include <math.h>
#include <stdint.h>

// Problem constants
#define NUM_O   5000
#define NUM_T   20000
#define DD      128
#define HH      512
#define GG      64
#define LL      5
#define K1      (3*DD)        // 384
#define N2      (2*HH+DD)     // 1152

// ================= scratch (__device__ globals) =================
__device__ float         g_ov    [NUM_O * DD];
__device__ float         g_nt    [NUM_T * N2];
__device__ float         g_pooled[NUM_O * HH];
__device__ float         g_counts[NUM_O];
__device__ float         g_invcnt[NUM_O];
__device__ float         g_scores[NUM_O];
__device__ float         g_gvec  [GG * DD];

__device__ __nv_bfloat16 g_th [NUM_T * K1], g_tl [NUM_T * K1];
__device__ __nv_bfloat16 g_hh [NUM_T * HH], g_hl [NUM_T * HH];
__device__ __nv_bfloat16 g_ph [NUM_O * HH], g_pl [NUM_O * HH];
__device__ __nv_bfloat16 g_h2h[NUM_O * HH], g_h2l[NUM_O * HH];

// transposed+split weights: [L, N, K]
__device__ __nv_bfloat16 g_w1h[LL * HH * K1], g_w1l[LL * HH * K1];
__device__ __nv_bfloat16 g_w2h[LL * N2 * HH], g_w2l[LL * N2 * HH];
__device__ __nv_bfloat16 g_w3h[LL * HH * HH], g_w3l[LL * HH * HH];
__device__ __nv_bfloat16 g_w4h[LL * DD * HH], g_w4l[LL * DD * HH];

__device__ __forceinline__ void f32split(float v, __nv_bfloat16& h, __nv_bfloat16& l) {
    h = __float2bfloat16(v);
    l = __float2bfloat16(v - __bfloat162float(h));
}

__device__ __forceinline__ uint32_t smem_u32(const void* p) {
    uint32_t a;
    asm("{ .reg .u64 t; cvta.to.shared.u64 t, %1; cvt.u32.u64 %0, t; }" : "=r"(a) : "l"(p));
    return a;
}

// ================= glue kernels =================
__global__ void zero_kernel(float* p, int n) {
    int i = blockIdx.x * blockDim.x + threadIdx.x;
    if (i < n) p[i] = 0.f;
}

__global__ void gather_ov_init(const float* __restrict__ obj_emb,
                               const int* __restrict__ objs,
                               float* __restrict__ ov) {
    int i = blockIdx.x, d = threadIdx.x;
    ov[i * DD + d] = obj_emb[objs[i] * DD + d];
}

__global__ void count_kernel(const int* __restrict__ trip, float* __restrict__ counts) {
    int i = blockIdx.x * blockDim.x + threadIdx.x;
    if (i < NUM_T) {
        atomicAdd(&counts[trip[3 * i + 0]], 1.f);
        atomicAdd(&counts[trip[3 * i + 2]], 1.f);
    }
}

__global__ void inv_kernel(const float* __restrict__ counts, float* __restrict__ inv) {
    int i = blockIdx.x * blockDim.x + threadIdx.x;
    if (i < NUM_O) inv[i] = 1.f / fmaxf(counts[i], 1.f);
}

// W [L,K,N] fp32 -> Wt [L,N,K] bf16 hi/lo (tiled transpose)
__global__ void wtrans_split(const float* __restrict__ w,
                             __nv_bfloat16* __restrict__ oh,
                             __nv_bfloat16* __restrict__ ol, int K, int N) {
    __shared__ float tile[32][33];
    int l = blockIdx.z;
    int k0 = blockIdx.y * 32, n0 = blockIdx.x * 32;
    const float* wl = w + (size_t)l * K * N;
    tile[threadIdx.y][threadIdx.x] = wl[(size_t)(k0 + threadIdx.y) * N + n0 + threadIdx.x];
    __syncthreads();
    int on = n0 + threadIdx.y, ok = k0 + threadIdx.x;
    float v = tile[threadIdx.x][threadIdx.y];
    __nv_bfloat16 h, lo; f32split(v, h, lo);
    size_t idx = ((size_t)l * N + on) * K + ok;
    oh[idx] = h; ol[idx] = lo;
}

__global__ void build_t(const float* __restrict__ ov,
                        const float* __restrict__ pred_emb,
                        const float* __restrict__ nt,
                        const int* __restrict__ trip,
                        __nv_bfloat16* __restrict__ th,
                        __nv_bfloat16* __restrict__ tl, int use_emb) {
    int i = blockIdx.x, d = threadIdx.x;
    int s = trip[3 * i + 0];
    int p = trip[3 * i + 1];
    int o = trip[3 * i + 2];
    float sv = ov[s * DD + d];
    float pv = use_emb ? pred_emb[p * DD + d] : nt[(size_t)i * N2 + HH + d];
    float ovv = ov[o * DD + d];
    size_t base = (size_t)i * K1;
    __nv_bfloat16 h, l;
    f32split(sv, h, l);  th[base + d] = h;           tl[base + d] = l;
    f32split(pv, h, l);  th[base + DD + d] = h;      tl[base + DD + d] = l;
    f32split(ovv, h, l); th[base + 2*DD + d] = h;    tl[base + 2*DD + d] = l;
}

__global__ void scatter_kernel(const int* __restrict__ trip,
                               const float* __restrict__ nt,
                               float* __restrict__ pooled) {
    int i = blockIdx.x;
    int j = threadIdx.x;            // 0..255
    const float* base = nt + (size_t)i * N2;
    if (j < 128) {
        int s = trip[3 * i + 0];
        float4 v = *reinterpret_cast<const float4*>(base + j * 4);
        float* dst = pooled + (size_t)s * HH + j * 4;
        atomicAdd(dst + 0, v.x); atomicAdd(dst + 1, v.y);
        atomicAdd(dst + 2, v.z); atomicAdd(dst + 3, v.w);
    } else {
        int jo = j - 128;
        int o = trip[3 * i + 2];
        float4 v = *reinterpret_cast<const float4*>(base + HH + DD + jo * 4);
        float* dst = pooled + (size_t)o * HH + jo * 4;
        atomicAdd(dst + 0, v.x); atomicAdd(dst + 1, v.y);
        atomicAdd(dst + 2, v.z); atomicAdd(dst + 3, v.w);
    }
}

__global__ void scale_split(const float* __restrict__ pooled, const float* __restrict__ inv,
                            __nv_bfloat16* __restrict__ ph, __nv_bfloat16* __restrict__ pl, int n) {
    int i = blockIdx.x * blockDim.x + threadIdx.x;
    if (i < n) {
        float v = pooled[i] * inv[i >> 9];
        __nv_bfloat16 h, l; f32split(v, h, l);
        ph[i] = h; pl[i] = l;
    }
}

// ================= HMMA GEMM =================
// C[M,N] = relu(A[M,K] @ B[N,K]^T + bias), 3-term bf16 split, fp32 accum.
// OUT_MODE 0: fp32 out; 1: bf16 hi/lo pair out.
#define BM   128
#define BN   128
#define BK   32
// smem stage layout (bytes): each buffer 128 rows x 64B
#define OFF_AH  0
#define OFF_AL  8192
#define OFF_BH  16384
#define OFF_BL  24576
#define STAGE   32768
#define SMEM_DYN (2*STAGE)

#define CP_ASYNC16(dst, src, sz) \
    asm volatile("cp.async.cg.shared.global [%0], [%1], 16, %2;" :: "r"(dst), "l"(src), "r"(sz))
#define CP_COMMIT() asm volatile("cp.async.commit_group;")
#define LDSM_X4(R0,R1,R2,R3,ADDR) \
    asm volatile("ldmatrix.sync.aligned.m8n8.x4.shared.b16 {%0,%1,%2,%3}, [%4];" \
                 : "=r"(R0),"=r"(R1),"=r"(R2),"=r"(R3) : "r"(ADDR))
#define MMA16816(C,A0,A1,A2,A3,B0,B1) \
    asm volatile("mma.sync.aligned.m16n8k16.row.col.f32.bf16.bf16.f32 " \
                 "{%0,%1,%2,%3},{%4,%5,%6,%7},{%8,%9},{%0,%1,%2,%3};" \
                 : "+f"((C)[0]),"+f"((C)[1]),"+f"((C)[2]),"+f"((C)[3]) \
                 : "r"(A0),"r"(A1),"r"(A2),"r"(A3),"r"(B0),"r"(B1))

// swizzled smem byte offset for (row, 16B-chunk c): row*64 + ((c ^ (row&3))<<4)
__device__ __forceinline__ uint32_t sw_off(int row, int c) {
    return (uint32_t)(row * 64 + (((c ^ (row & 3))) << 4));
}

__device__ __forceinline__ void ld_stage(
    uint32_t st,   // smem u32 address of stage base
    const __nv_bfloat16* __restrict__ Ah, const __nv_bfloat16* __restrict__ Al,
    const __nv_bfloat16* __restrict__ Bh, const __nv_bfloat16* __restrict__ Bl,
    int bm, int bn, int k0, int M, int K, int tid)
{
#pragma unroll
    for (int rep = 0; rep < 2; rep++) {
        int lin = tid + rep * 256;       // 0..511
        int row = lin >> 2;
        int c   = lin & 3;
        uint32_t so = sw_off(row, c);
        // A rows (guard M)
        {
            int gr = bm + row;
            uint32_t sz = (gr < M) ? 16u : 0u;
            size_t srow = (gr < M) ? (size_t)gr : 0;
            const char* sh = (const char*)(Ah + srow * K + k0 + c * 8);
            const char* sl = (const char*)(Al + srow * K + k0 + c * 8);
            CP_ASYNC16(st + OFF_AH + so, sh, sz);
            CP_ASYNC16(st + OFF_AL + so, sl, sz);
        }
        // B rows (N multiple of 128, no guard)
        {
            int gr = bn + row;
            const char* sh = (const char*)(Bh + (size_t)gr * K + k0 + c * 8);
            const char* sl = (const char*)(Bl + (size_t)gr * K + k0 + c * 8);
            CP_ASYNC16(st + OFF_BH + so, sh, 16u);
            CP_ASYNC16(st + OFF_BL + so, sl, 16u);
        }
    }
}

template <int OUT_MODE>
__global__ void __launch_bounds__(256)
gemm_hmma(const __nv_bfloat16* __restrict__ Ah, const __nv_bfloat16* __restrict__ Al,
          const __nv_bfloat16* __restrict__ Bh, const __nv_bfloat16* __restrict__ Bl,
          const float* __restrict__ bias,
          float* __restrict__ Cf,
          __nv_bfloat16* __restrict__ Ch, __nv_bfloat16* __restrict__ Cl,
          int M, int N, int K)
{
    extern __shared__ char smem[];
    uint32_t sb = smem_u32(smem);

    int tid = threadIdx.x;
    int wid = tid >> 5, lane = tid & 31;
    int wm = (wid & 1) * 64;        // warp m offset in tile
    int wn = (wid >> 1) * 32;       // warp n offset in tile
    int bm = blockIdx.y * BM;
    int bn = blockIdx.x * BN;
    const int NC = K / BK;

    float acc[4][4][4];
#pragma unroll
    for (int i = 0; i < 4; i++)
#pragma unroll
        for (int j = 0; j < 4; j++)
#pragma unroll
            for (int r = 0; r < 4; r++) acc[i][j][r] = 0.f;

    // precomputed per-lane ldmatrix row/chunk components
    int lrow8 = (lane & 7) + ((lane >> 3) & 1) * 8;   // row within 16-row group
    int lchunk = (lane >> 4);                          // 0 or 1 (k half within k16)

    ld_stage(sb, Ah, Al, Bh, Bl, bm, bn, 0, M, K, tid);
    CP_COMMIT();

    for (int kc = 0; kc < NC; kc++) {
        if (kc + 1 < NC) {
            ld_stage(sb + ((kc + 1) & 1) * STAGE, Ah, Al, Bh, Bl, bm, bn, (kc + 1) * BK, M, K, tid);
            CP_COMMIT();
            asm volatile("cp.async.wait_group 1;");
        } else {
            asm volatile("cp.async.wait_group 0;");
        }
        __syncthreads();

        uint32_t sa = sb + (kc & 1) * STAGE;
#pragma unroll
        for (int ks = 0; ks < 2; ks++) {          // two k16 steps in BK=32
            int c0 = ks * 2;                      // chunk base (16B chunks of 8 bf16)
            uint32_t ah[4][4], al[4][4], bh[4][2], bl[4][2];
            // A hi fragments
#pragma unroll
            for (int mt = 0; mt < 4; mt++) {
                int row = wm + mt * 16 + lrow8;
                uint32_t addr = sa + OFF_AH + sw_off(row, c0 + lchunk);
                LDSM_X4(ah[mt][0], ah[mt][1], ah[mt][2], ah[mt][3], addr);
            }
            // B hi fragments (x4 covers 16 n rows = 2 n-tiles)
#pragma unroll
            for (int np = 0; np < 2; np++) {
                int row = wn + np * 16 + lrow8;
                uint32_t addr = sa + OFF_BH + sw_off(row, c0 + lchunk);
                uint32_t r0, r1, r2, r3;
                LDSM_X4(r0, r1, r2, r3, addr);
                bh[2*np][0] = r0; bh[2*np+1][0] = r1;
                bh[2*np][1] = r2; bh[2*np+1][1] = r3;
            }
            // hi x hi
#pragma unroll
            for (int mt = 0; mt < 4; mt++)
#pragma unroll
                for (int nt = 0; nt < 4; nt++)
                    MMA16816(acc[mt][nt], ah[mt][0], ah[mt][1], ah[mt][2], ah[mt][3],
                             bh[nt][0], bh[nt][1]);
            // B lo
#pragma unroll
            for (int np = 0; np < 2; np++) {
                int row = wn + np * 16 + lrow8;
                uint32_t addr = sa + OFF_BL + sw_off(row, c0 + lchunk);
                uint32_t r0, r1, r2, r3;
                LDSM_X4(r0, r1, r2, r3, addr);
                bl[2*np][0] = r0; bl[2*np+1][0] = r1;
                bl[2*np][1] = r2; bl[2*np+1][1] = r3;
            }
            // hi x lo
#pragma unroll
            for (int mt = 0; mt < 4; mt++)
#pragma unroll
                for (int nt = 0; nt < 4; nt++)
                    MMA16816(acc[mt][nt], ah[mt][0], ah[mt][1], ah[mt][2], ah[mt][3],
                             bl[nt][0], bl[nt][1]);
            // A lo
#pragma unroll
            for (int mt = 0; mt < 4; mt++) {
                int row = wm + mt * 16 + lrow8;
                uint32_t addr = sa + OFF_AL + sw_off(row, c0 + lchunk);
                LDSM_X4(al[mt][0], al[mt][1], al[mt][2], al[mt][3], addr);
            }
            // lo x hi
#pragma unroll
            for (int mt = 0; mt < 4; mt++)
#pragma unroll
                for (int nt = 0; nt < 4; nt++)
                    MMA16816(acc[mt][nt], al[mt][0], al[mt][1], al[mt][2], al[mt][3],
                             bh[nt][0], bh[nt][1]);
        }
        __syncthreads();
    }

    // epilogue
    int r = lane >> 2, q = lane & 3;
#pragma unroll
    for (int mt = 0; mt < 4; mt++) {
        int row0 = bm + wm + mt * 16 + r;
        int row1 = row0 + 8;
#pragma unroll
        for (int nt = 0; nt < 4; nt++) {
            int col = bn + wn + nt * 8 + q * 2;
            float b0 = bias[col], b1 = bias[col + 1];
            float v00 = fmaxf(acc[mt][nt][0] + b0, 0.f);
            float v01 = fmaxf(acc[mt][nt][1] + b1, 0.f);
            float v10 = fmaxf(acc[mt][nt][2] + b0, 0.f);
            float v11 = fmaxf(acc[mt][nt][3] + b1, 0.f);
            if (OUT_MODE == 0) {
                if (row0 < M) *reinterpret_cast<float2*>(Cf + (size_t)row0 * N + col) = make_float2(v00, v01);
                if (row1 < M) *reinterpret_cast<float2*>(Cf + (size_t)row1 * N + col) = make_float2(v10, v11);
            } else {
                __nv_bfloat16 h0, l0, h1, l1;
                if (row0 < M) {
                    f32split(v00, h0, l0); f32split(v01, h1, l1);
                    __nv_bfloat162 hp; hp.x = h0; hp.y = h1;
                    __nv_bfloat162 lp; lp.x = l0; lp.y = l1;
                    *reinterpret_cast<__nv_bfloat162*>(Ch + (size_t)row0 * N + col) = hp;
                    *reinterpret_cast<__nv_bfloat162*>(Cl + (size_t)row0 * N + col) = lp;
                }
                if (row1 < M) {
                    f32split(v10, h0, l0); f32split(v11, h1, l1);
                    __nv_bfloat162 hp; hp.x = h0; hp.y = h1;
                    __nv_bfloat162 lp; lp.x = l0; lp.y = l1;
                    *reinterpret_cast<__nv_bfloat162*>(Ch + (size_t)row1 * N + col) = hp;
                    *reinterpret_cast<__nv_bfloat162*>(Cl + (size_t)row1 * N + col) = lp;
                }
            }
        }
    }
}

// ================= attention epilogue =================
__global__ void scores_kernel(const float* __restrict__ ov,
                              const float* __restrict__ att_w,
                              const float* __restrict__ att_b,
                              float* __restrict__ scores) {
    int gid = blockIdx.x * blockDim.x + threadIdx.x;
    int w = gid >> 5, lane = gid & 31;
    if (w >= NUM_O) return;
    float sum = 0.f;
#pragma unroll
    for (int d = lane; d < DD; d += 32) sum += ov[(size_t)w * DD + d] * att_w[d];
#pragma unroll
    for (int off = 16; off; off >>= 1) sum += __shfl_down_sync(0xffffffff, sum, off);
    if (lane == 0) scores[w] = sum + att_b[0];
}

__global__ void segment_kernel(const float* __restrict__ scores,
                               const int* __restrict__ img,
                               const float* __restrict__ ov,
                               float* __restrict__ gvec) {
    int g = blockIdx.x, t = threadIdx.x;   // 128 threads
    __shared__ float sred[128];
    __shared__ int ired[128];

    float m = -3.4e38f;
    int lo = NUM_O, hi = -1;
    for (int i = t; i < NUM_O; i += 128) {
        if (img[i] == g) {
            m = fmaxf(m, scores[i]);
            lo = min(lo, i);
            hi = max(hi, i);
        }
    }
    sred[t] = m; __syncthreads();
    for (int s = 64; s > 0; s >>= 1) { if (t < s) sred[t] = fmaxf(sred[t], sred[t + s]); __syncthreads(); }
    m = sred[0]; __syncthreads();
    ired[t] = lo; __syncthreads();
    for (int s = 64; s > 0; s >>= 1) { if (t < s) ired[t] = min(ired[t], ired[t + s]); __syncthreads(); }
    lo = ired[0]; __syncthreads();
    ired[t] = hi; __syncthreads();
    for (int s = 64; s > 0; s >>= 1) { if (t < s) ired[t] = max(ired[t], ired[t + s]); __syncthreads(); }
    hi = ired[0]; __syncthreads();

    float z = 0.f;
    for (int i = lo + t; i <= hi; i += 128)
        if (img[i] == g) z += expf(scores[i] - m);
    sred[t] = z; __syncthreads();
    for (int s = 64; s > 0; s >>= 1) { if (t < s) sred[t] += sred[t + s]; __syncthreads(); }
    z = sred[0];
    float invz = 1.f / z;

    float acc = 0.f;
    for (int i = lo; i <= hi; i++) {
        if (img[i] == g)
            acc += expf(scores[i] - m) * invz * ov[(size_t)i * DD + t];
    }
    gvec[g * DD + t] = acc;
}

__global__ void concat_kernel(const float* __restrict__ ov,
                              const float* __restrict__ gvec,
                              const int* __restrict__ img,
                              float* __restrict__ out) {
    int i = blockIdx.x, t = threadIdx.x;   // 256 threads
    if (t < DD) out[(size_t)i * 256 + t] = ov[(size_t)i * DD + t];
    else        out[(size_t)i * 256 + t] = gvec[img[i] * DD + (t - DD)];
}

// ================= launch =================
extern "C" void kernel_launch(void* const* d_in, const int* in_sizes, int n_in,
                              void* d_out, int out_size) {
    const int*   objs     = (const int*)d_in[0];
    const int*   trip     = (const int*)d_in[1];
    const int*   img      = (const int*)d_in[2];
    const float* obj_emb  = (const float*)d_in[3];
    const float* pred_emb = (const float*)d_in[4];
    const float* n1w1     = (const float*)d_in[5];
    const float* n1b1     = (const float*)d_in[6];
    const float* n1w2     = (const float*)d_in[7];
    const float* n1b2     = (const float*)d_in[8];
    const float* n2w1     = (const float*)d_in[9];
    const float* n2b1     = (const float*)d_in[10];
    const float* n2w2     = (const float*)d_in[11];
    const float* n2b2     = (const float*)d_in[12];
    const float* att_w    = (const float*)d_in[13];
    const float* att_b    = (const float*)d_in[14];
    float* out = (float*)d_out;

    float *ov, *nt, *pooled, *counts, *inv, *scores, *gvec;
    __nv_bfloat16 *th, *tl, *hh, *hl, *ph, *pl, *h2h, *h2l;
    __nv_bfloat16 *w1h, *w1l, *w2h, *w2l, *w3h, *w3l, *w4h, *w4l;
    cudaGetSymbolAddress((void**)&ov,     g_ov);
    cudaGetSymbolAddress((void**)&nt,     g_nt);
    cudaGetSymbolAddress((void**)&pooled, g_pooled);
    cudaGetSymbolAddress((void**)&counts, g_counts);
    cudaGetSymbolAddress((void**)&inv,    g_invcnt);
    cudaGetSymbolAddress((void**)&scores, g_scores);
    cudaGetSymbolAddress((void**)&gvec,   g_gvec);
    cudaGetSymbolAddress((void**)&th,  g_th);  cudaGetSymbolAddress((void**)&tl,  g_tl);
    cudaGetSymbolAddress((void**)&hh,  g_hh);  cudaGetSymbolAddress((void**)&hl,  g_hl);
    cudaGetSymbolAddress((void**)&ph,  g_ph);  cudaGetSymbolAddress((void**)&pl,  g_pl);
    cudaGetSymbolAddress((void**)&h2h, g_h2h); cudaGetSymbolAddress((void**)&h2l, g_h2l);
    cudaGetSymbolAddress((void**)&w1h, g_w1h); cudaGetSymbolAddress((void**)&w1l, g_w1l);
    cudaGetSymbolAddress((void**)&w2h, g_w2h); cudaGetSymbolAddress((void**)&w2l, g_w2l);
    cudaGetSymbolAddress((void**)&w3h, g_w3h); cudaGetSymbolAddress((void**)&w3l, g_w3l);
    cudaGetSymbolAddress((void**)&w4h, g_w4h); cudaGetSymbolAddress((void**)&w4l, g_w4l);

    cudaFuncSetAttribute(gemm_hmma<0>, cudaFuncAttributeMaxDynamicSharedMemorySize, SMEM_DYN);
    cudaFuncSetAttribute(gemm_hmma<1>, cudaFuncAttributeMaxDynamicSharedMemorySize, SMEM_DYN);

    // weight preprocessing: [L,K,N] fp32 -> [L,N,K] bf16 hi/lo
    wtrans_split<<<dim3(HH/32, K1/32, LL), dim3(32,32)>>>(n1w1, w1h, w1l, K1, HH);
    wtrans_split<<<dim3(N2/32, HH/32, LL), dim3(32,32)>>>(n1w2, w2h, w2l, HH, N2);
    wtrans_split<<<dim3(HH/32, HH/32, LL), dim3(32,32)>>>(n2w1, w3h, w3l, HH, HH);
    wtrans_split<<<dim3(DD/32, HH/32, LL), dim3(32,32)>>>(n2w2, w4h, w4l, HH, DD);

    gather_ov_init<<<NUM_O, DD>>>(obj_emb, objs, ov);
    zero_kernel<<<(NUM_O + 255) / 256, 256>>>(counts, NUM_O);
    count_kernel<<<(NUM_T + 255) / 256, 256>>>(trip, counts);
    inv_kernel<<<(NUM_O + 255) / 256, 256>>>(counts, inv);

    const int mT = (NUM_T + BM - 1) / BM;   // 157
    const int mO = (NUM_O + BM - 1) / BM;   // 40

    for (int l = 0; l < LL; l++) {
        build_t<<<NUM_T, DD>>>(ov, pred_emb, nt, trip, th, tl, l == 0 ? 1 : 0);

        // GEMM1: h = relu(t @ w1 + b1), out bf16 pair   [20000,512,K=384]
        gemm_hmma<1><<<dim3(HH/BN, mT), 256, SMEM_DYN>>>(
            th, tl, w1h + (size_t)l*HH*K1, w1l + (size_t)l*HH*K1,
            n1b1 + (size_t)l*HH, nullptr, hh, hl, NUM_T, HH, K1);

        // GEMM2: nt = relu(h @ w2 + b2), out fp32       [20000,1152,K=512]
        gemm_hmma<0><<<dim3(N2/BN, mT), 256, SMEM_DYN>>>(
            hh, hl, w2h + (size_t)l*N2*HH, w2l + (size_t)l*N2*HH,
            n1b2 + (size_t)l*N2, nt, nullptr, nullptr, NUM_T, N2, HH);

        zero_kernel<<<(NUM_O * HH + 255) / 256, 256>>>(pooled, NUM_O * HH);
        scatter_kernel<<<NUM_T, 256>>>(trip, nt, pooled);
        scale_split<<<(NUM_O * HH + 255) / 256, 256>>>(pooled, inv, ph, pl, NUM_O * HH);

        // GEMM3: h2 = relu(pooled @ w3 + b3), out bf16 pair [5000,512,K=512]
        gemm_hmma<1><<<dim3(HH/BN, mO), 256, SMEM_DYN>>>(
            ph, pl, w3h + (size_t)l*HH*HH, w3l + (size_t)l*HH*HH,
            n2b1 + (size_t)l*HH, nullptr, h2h, h2l, NUM_O, HH, HH);

        // GEMM4: ov = relu(h2 @ w4 + b4), out fp32      [5000,128,K=512]
        gemm_hmma<0><<<dim3(DD/BN, mO), 256, SMEM_DYN>>>(
            h2h, h2l, w4h + (size_t)l*DD*HH, w4l + (size_t)l*DD*HH,
            n2b2 + (size_t)l*DD, ov, nullptr, nullptr, NUM_O, DD, HH);
    }

    scores_kernel<<<(NUM_O * 32 + 255) / 256, 256>>>(ov, att_w, att_b, scores);
    segment_kernel<<<GG, 128>>>(scores, img, ov, gvec);
    concat_kernel<<<NUM_O, 256>>>(ov, gvec, img, out);
}

// round 4
// speedup vs baseline: 2.6129x; 1.1075x over previous
#include <cuda_runtime.h>
#include <cuda_bf16.h>
#include <math.h>
#include <stdint.h>

// Problem constants
#define NUM_O   5000
#define NUM_T   20000
#define DD      128
#define HH      512
#define GG      64
#define LL      5
#define K1      (3*DD)        // 384
#define N2      (2*HH+DD)     // 1152

typedef __nv_bfloat16 bf16;

// ================= scratch (__device__ globals) =================
__device__ float g_ov    [NUM_O * DD];
__device__ float g_pooled[NUM_O * HH];
__device__ float g_counts[NUM_O];
__device__ float g_invcnt[NUM_O];
__device__ float g_scores[NUM_O];
__device__ float g_gvec  [GG * DD];

__device__ bf16 g_ovh[NUM_O * DD], g_ovl[NUM_O * DD];
__device__ bf16 g_pvh[NUM_T * DD], g_pvl[NUM_T * DD];
__device__ bf16 g_hh [NUM_T * HH], g_hl [NUM_T * HH];
__device__ bf16 g_ph [NUM_O * HH], g_pl [NUM_O * HH];
__device__ bf16 g_h2h[NUM_O * HH], g_h2l[NUM_O * HH];

// transposed+split weights: [L, N, K]
__device__ bf16 g_w1h[LL * HH * K1], g_w1l[LL * HH * K1];
__device__ bf16 g_w2h[LL * N2 * HH], g_w2l[LL * N2 * HH];
__device__ bf16 g_w3h[LL * HH * HH], g_w3l[LL * HH * HH];
__device__ bf16 g_w4h[LL * DD * HH], g_w4l[LL * DD * HH];

__device__ __forceinline__ void f32split(float v, bf16& h, bf16& l) {
    h = __float2bfloat16(v);
    l = __float2bfloat16(v - __bfloat162float(h));
}

__device__ __forceinline__ uint32_t smem_u32(const void* p) {
    uint32_t a;
    asm("{ .reg .u64 t; cvta.to.shared.u64 t, %1; cvt.u32.u64 %0, t; }" : "=r"(a) : "l"(p));
    return a;
}

// ================= glue kernels =================
__global__ void zero_kernel(float* p, int n) {
    int i = blockIdx.x * blockDim.x + threadIdx.x;
    if (i < n) p[i] = 0.f;
}

__global__ void gather_ov_init(const float* __restrict__ obj_emb,
                               const int* __restrict__ objs,
                               bf16* __restrict__ ovh, bf16* __restrict__ ovl) {
    int i = blockIdx.x, d = threadIdx.x;
    float v = obj_emb[objs[i] * DD + d];
    bf16 h, l; f32split(v, h, l);
    ovh[i * DD + d] = h; ovl[i * DD + d] = l;
}

__global__ void gather_pv0(const float* __restrict__ pred_emb,
                           const int* __restrict__ trip,
                           bf16* __restrict__ pvh, bf16* __restrict__ pvl) {
    int i = blockIdx.x, d = threadIdx.x;
    int p = trip[3 * i + 1];
    float v = pred_emb[p * DD + d];
    bf16 h, l; f32split(v, h, l);
    pvh[i * DD + d] = h; pvl[i * DD + d] = l;
}

__global__ void count_kernel(const int* __restrict__ trip, float* __restrict__ counts) {
    int i = blockIdx.x * blockDim.x + threadIdx.x;
    if (i < NUM_T) {
        atomicAdd(&counts[trip[3 * i + 0]], 1.f);
        atomicAdd(&counts[trip[3 * i + 2]], 1.f);
    }
}

__global__ void inv_kernel(const float* __restrict__ counts, float* __restrict__ inv) {
    int i = blockIdx.x * blockDim.x + threadIdx.x;
    if (i < NUM_O) inv[i] = 1.f / fmaxf(counts[i], 1.f);
}

// W [L,K,N] fp32 -> Wt [L,N,K] bf16 hi/lo (tiled transpose)
__global__ void wtrans_split(const float* __restrict__ w,
                             bf16* __restrict__ oh,
                             bf16* __restrict__ ol, int K, int N) {
    __shared__ float tile[32][33];
    int l = blockIdx.z;
    int k0 = blockIdx.y * 32, n0 = blockIdx.x * 32;
    const float* wl = w + (size_t)l * K * N;
    tile[threadIdx.y][threadIdx.x] = wl[(size_t)(k0 + threadIdx.y) * N + n0 + threadIdx.x];
    __syncthreads();
    int on = n0 + threadIdx.y, ok = k0 + threadIdx.x;
    float v = tile[threadIdx.x][threadIdx.y];
    bf16 h, lo; f32split(v, h, lo);
    size_t idx = ((size_t)l * N + on) * K + ok;
    oh[idx] = h; ol[idx] = lo;
}

__global__ void scale_split(const float* __restrict__ pooled, const float* __restrict__ inv,
                            bf16* __restrict__ ph, bf16* __restrict__ pl, int n) {
    int i = blockIdx.x * blockDim.x + threadIdx.x;
    if (i < n) {
        float v = pooled[i] * inv[i >> 9];
        bf16 h, l; f32split(v, h, l);
        ph[i] = h; pl[i] = l;
    }
}

// ================= HMMA GEMM =================
// C[M,N] = relu(A[M,K] @ B[N,K]^T + bias), 3-term bf16 split, fp32 accum.
// A_MODE 0: A = Ah/Al [M,K].  A_MODE 1: A gathered: cols 0-127 ov[s], 128-255 pv[i], 256-383 ov[o].
// OUT_MODE 1: bf16 hi/lo pair. 2: fp32 + bf16 pair. 3: scatter (pooled atomics + pv block).
#define BM   128
#define BN   128
#define BK   32
#define OFF_AH  0
#define OFF_AL  8192
#define OFF_BH  16384
#define OFF_BL  24576
#define STAGE   32768
#define SMEM_DYN (2*STAGE)

#define CP_ASYNC16(dst, src, sz) \
    asm volatile("cp.async.cg.shared.global [%0], [%1], 16, %2;" :: "r"(dst), "l"(src), "r"(sz))
#define CP_COMMIT() asm volatile("cp.async.commit_group;")
#define LDSM_X4(R0,R1,R2,R3,ADDR) \
    asm volatile("ldmatrix.sync.aligned.m8n8.x4.shared.b16 {%0,%1,%2,%3}, [%4];" \
                 : "=r"(R0),"=r"(R1),"=r"(R2),"=r"(R3) : "r"(ADDR))
#define MMA16816(C,A0,A1,A2,A3,B0,B1) \
    asm volatile("mma.sync.aligned.m16n8k16.row.col.f32.bf16.bf16.f32 " \
                 "{%0,%1,%2,%3},{%4,%5,%6,%7},{%8,%9},{%0,%1,%2,%3};" \
                 : "+f"((C)[0]),"+f"((C)[1]),"+f"((C)[2]),"+f"((C)[3]) \
                 : "r"(A0),"r"(A1),"r"(A2),"r"(A3),"r"(B0),"r"(B1))

__device__ __forceinline__ uint32_t sw_off(int row, int c) {
    return (uint32_t)(row * 64 + (((c ^ (row & 3))) << 4));
}

template <int A_MODE>
__device__ __forceinline__ void ld_stage(
    uint32_t st,
    const bf16* __restrict__ Ah, const bf16* __restrict__ Al,
    const bf16* __restrict__ OVh, const bf16* __restrict__ OVl,
    const bf16* __restrict__ PVh, const bf16* __restrict__ PVl,
    const int* __restrict__ trip,
    const bf16* __restrict__ Bh, const bf16* __restrict__ Bl,
    int bm, int bn, int k0, int M, int K, int tid)
{
    int seg = k0 >> 7;              // which 128-col segment (A_MODE 1)
    int koff_base = k0 & 127;
#pragma unroll
    for (int rep = 0; rep < 2; rep++) {
        int lin = tid + rep * 256;       // 0..511
        int row = lin >> 2;
        int c   = lin & 3;
        uint32_t so = sw_off(row, c);
        // A rows (guard M)
        {
            int gr = bm + row;
            bool ok = gr < M;
            uint32_t sz = ok ? 16u : 0u;
            const char *sh, *sl;
            if (A_MODE == 0) {
                size_t srow = ok ? (size_t)gr : 0;
                sh = (const char*)(Ah + srow * K + k0 + c * 8);
                sl = (const char*)(Al + srow * K + k0 + c * 8);
            } else {
                int gi = ok ? gr : 0;
                int koff = koff_base + c * 8;
                size_t off;
                if (seg == 0) {
                    int s = __ldg(&trip[3 * gi + 0]);
                    off = (size_t)s * DD + koff;
                    sh = (const char*)(OVh + off); sl = (const char*)(OVl + off);
                } else if (seg == 1) {
                    off = (size_t)gi * DD + koff;
                    sh = (const char*)(PVh + off); sl = (const char*)(PVl + off);
                } else {
                    int o = __ldg(&trip[3 * gi + 2]);
                    off = (size_t)o * DD + koff;
                    sh = (const char*)(OVh + off); sl = (const char*)(OVl + off);
                }
            }
            CP_ASYNC16(st + OFF_AH + so, sh, sz);
            CP_ASYNC16(st + OFF_AL + so, sl, sz);
        }
        // B rows (N multiple of 128, no guard)
        {
            int gr = bn + row;
            const char* sh = (const char*)(Bh + (size_t)gr * K + k0 + c * 8);
            const char* sl = (const char*)(Bl + (size_t)gr * K + k0 + c * 8);
            CP_ASYNC16(st + OFF_BH + so, sh, 16u);
            CP_ASYNC16(st + OFF_BL + so, sl, 16u);
        }
    }
}

template <int A_MODE, int OUT_MODE>
__global__ void __launch_bounds__(256)
gemm_hmma(const bf16* __restrict__ Ah, const bf16* __restrict__ Al,
          const bf16* __restrict__ OVh, const bf16* __restrict__ OVl,
          const bf16* __restrict__ PVh, const bf16* __restrict__ PVl,
          const int* __restrict__ trip,
          const bf16* __restrict__ Bh, const bf16* __restrict__ Bl,
          const float* __restrict__ bias,
          float* __restrict__ Cf,
          bf16* __restrict__ Ch, bf16* __restrict__ Cl,
          float* __restrict__ pooled,
          bf16* __restrict__ Pvh, bf16* __restrict__ Pvl,
          int M, int N, int K)
{
    extern __shared__ char smem[];
    uint32_t sb = smem_u32(smem);

    int tid = threadIdx.x;
    int wid = tid >> 5, lane = tid & 31;
    int wm = (wid & 1) * 64;
    int wn = (wid >> 1) * 32;
    int bm = blockIdx.y * BM;
    int bn = blockIdx.x * BN;
    const int NC = K / BK;

    float acc[4][4][4];
#pragma unroll
    for (int i = 0; i < 4; i++)
#pragma unroll
        for (int j = 0; j < 4; j++)
#pragma unroll
            for (int r = 0; r < 4; r++) acc[i][j][r] = 0.f;

    int lrow8 = (lane & 7) + ((lane >> 3) & 1) * 8;
    int lchunk = (lane >> 4);

    ld_stage<A_MODE>(sb, Ah, Al, OVh, OVl, PVh, PVl, trip, Bh, Bl, bm, bn, 0, M, K, tid);
    CP_COMMIT();

    for (int kc = 0; kc < NC; kc++) {
        if (kc + 1 < NC) {
            ld_stage<A_MODE>(sb + ((kc + 1) & 1) * STAGE, Ah, Al, OVh, OVl, PVh, PVl, trip,
                             Bh, Bl, bm, bn, (kc + 1) * BK, M, K, tid);
            CP_COMMIT();
            asm volatile("cp.async.wait_group 1;");
        } else {
            asm volatile("cp.async.wait_group 0;");
        }
        __syncthreads();

        uint32_t sa = sb + (kc & 1) * STAGE;
#pragma unroll
        for (int ks = 0; ks < 2; ks++) {
            int c0 = ks * 2;
            uint32_t ah[4][4], al[4][4], bh[4][2], bl[4][2];
#pragma unroll
            for (int mt = 0; mt < 4; mt++) {
                int row = wm + mt * 16 + lrow8;
                uint32_t addr = sa + OFF_AH + sw_off(row, c0 + lchunk);
                LDSM_X4(ah[mt][0], ah[mt][1], ah[mt][2], ah[mt][3], addr);
            }
#pragma unroll
            for (int np = 0; np < 2; np++) {
                int row = wn + np * 16 + lrow8;
                uint32_t addr = sa + OFF_BH + sw_off(row, c0 + lchunk);
                uint32_t r0, r1, r2, r3;
                LDSM_X4(r0, r1, r2, r3, addr);
                bh[2*np][0] = r0; bh[2*np+1][0] = r1;
                bh[2*np][1] = r2; bh[2*np+1][1] = r3;
            }
#pragma unroll
            for (int mt = 0; mt < 4; mt++)
#pragma unroll
                for (int nt = 0; nt < 4; nt++)
                    MMA16816(acc[mt][nt], ah[mt][0], ah[mt][1], ah[mt][2], ah[mt][3],
                             bh[nt][0], bh[nt][1]);
#pragma unroll
            for (int np = 0; np < 2; np++) {
                int row = wn + np * 16 + lrow8;
                uint32_t addr = sa + OFF_BL + sw_off(row, c0 + lchunk);
                uint32_t r0, r1, r2, r3;
                LDSM_X4(r0, r1, r2, r3, addr);
                bl[2*np][0] = r0; bl[2*np+1][0] = r1;
                bl[2*np][1] = r2; bl[2*np+1][1] = r3;
            }
#pragma unroll
            for (int mt = 0; mt < 4; mt++)
#pragma unroll
                for (int nt = 0; nt < 4; nt++)
                    MMA16816(acc[mt][nt], ah[mt][0], ah[mt][1], ah[mt][2], ah[mt][3],
                             bl[nt][0], bl[nt][1]);
#pragma unroll
            for (int mt = 0; mt < 4; mt++) {
                int row = wm + mt * 16 + lrow8;
                uint32_t addr = sa + OFF_AL + sw_off(row, c0 + lchunk);
                LDSM_X4(al[mt][0], al[mt][1], al[mt][2], al[mt][3], addr);
            }
#pragma unroll
            for (int mt = 0; mt < 4; mt++)
#pragma unroll
                for (int nt = 0; nt < 4; nt++)
                    MMA16816(acc[mt][nt], al[mt][0], al[mt][1], al[mt][2], al[mt][3],
                             bh[nt][0], bh[nt][1]);
        }
        __syncthreads();
    }

    // epilogue
    int r = lane >> 2, q = lane & 3;
#pragma unroll
    for (int mt = 0; mt < 4; mt++) {
        int row0 = bm + wm + mt * 16 + r;
        int row1 = row0 + 8;
        int i0 = 0, i1 = 0;
        if (OUT_MODE == 3 && bn != 512) {
            int tcol = (bn < 512) ? 0 : 2;
            if (row0 < M) i0 = __ldg(&trip[3 * row0 + tcol]);
            if (row1 < M) i1 = __ldg(&trip[3 * row1 + tcol]);
        }
#pragma unroll
        for (int nt = 0; nt < 4; nt++) {
            int col = bn + wn + nt * 8 + q * 2;
            float b0 = bias[col], b1 = bias[col + 1];
            float v00 = fmaxf(acc[mt][nt][0] + b0, 0.f);
            float v01 = fmaxf(acc[mt][nt][1] + b1, 0.f);
            float v10 = fmaxf(acc[mt][nt][2] + b0, 0.f);
            float v11 = fmaxf(acc[mt][nt][3] + b1, 0.f);
            if (OUT_MODE == 1 || OUT_MODE == 2) {
                bf16 h0, l0, h1, l1;
                if (row0 < M) {
                    if (OUT_MODE == 2)
                        *reinterpret_cast<float2*>(Cf + (size_t)row0 * N + col) = make_float2(v00, v01);
                    f32split(v00, h0, l0); f32split(v01, h1, l1);
                    __nv_bfloat162 hp; hp.x = h0; hp.y = h1;
                    __nv_bfloat162 lp; lp.x = l0; lp.y = l1;
                    *reinterpret_cast<__nv_bfloat162*>(Ch + (size_t)row0 * N + col) = hp;
                    *reinterpret_cast<__nv_bfloat162*>(Cl + (size_t)row0 * N + col) = lp;
                }
                if (row1 < M) {
                    if (OUT_MODE == 2)
                        *reinterpret_cast<float2*>(Cf + (size_t)row1 * N + col) = make_float2(v10, v11);
                    f32split(v10, h0, l0); f32split(v11, h1, l1);
                    __nv_bfloat162 hp; hp.x = h0; hp.y = h1;
                    __nv_bfloat162 lp; lp.x = l0; lp.y = l1;
                    *reinterpret_cast<__nv_bfloat162*>(Ch + (size_t)row1 * N + col) = hp;
                    *reinterpret_cast<__nv_bfloat162*>(Cl + (size_t)row1 * N + col) = lp;
                }
            } else if (OUT_MODE == 3) {
                if (bn == 512) {
                    // pv block: cols 512..639 -> pv[row, col-512]
                    int pc = col - 512;
                    bf16 h0, l0, h1, l1;
                    if (row0 < M) {
                        f32split(v00, h0, l0); f32split(v01, h1, l1);
                        __nv_bfloat162 hp; hp.x = h0; hp.y = h1;
                        __nv_bfloat162 lp; lp.x = l0; lp.y = l1;
                        *reinterpret_cast<__nv_bfloat162*>(Pvh + (size_t)row0 * DD + pc) = hp;
                        *reinterpret_cast<__nv_bfloat162*>(Pvl + (size_t)row0 * DD + pc) = lp;
                    }
                    if (row1 < M) {
                        f32split(v10, h0, l0); f32split(v11, h1, l1);
                        __nv_bfloat162 hp; hp.x = h0; hp.y = h1;
                        __nv_bfloat162 lp; lp.x = l0; lp.y = l1;
                        *reinterpret_cast<__nv_bfloat162*>(Pvh + (size_t)row1 * DD + pc) = hp;
                        *reinterpret_cast<__nv_bfloat162*>(Pvl + (size_t)row1 * DD + pc) = lp;
                    }
                } else {
                    int pc = (bn < 512) ? col : (col - 640);
                    if (row0 < M) {
                        float* dst = pooled + (size_t)i0 * HH + pc;
                        atomicAdd(dst, v00); atomicAdd(dst + 1, v01);
                    }
                    if (row1 < M) {
                        float* dst = pooled + (size_t)i1 * HH + pc;
                        atomicAdd(dst, v10); atomicAdd(dst + 1, v11);
                    }
                }
            }
        }
    }
}

// ================= attention epilogue =================
__global__ void scores_kernel(const float* __restrict__ ov,
                              const float* __restrict__ att_w,
                              const float* __restrict__ att_b,
                              float* __restrict__ scores) {
    int gid = blockIdx.x * blockDim.x + threadIdx.x;
    int w = gid >> 5, lane = gid & 31;
    if (w >= NUM_O) return;
    float sum = 0.f;
#pragma unroll
    for (int d = lane; d < DD; d += 32) sum += ov[(size_t)w * DD + d] * att_w[d];
#pragma unroll
    for (int off = 16; off; off >>= 1) sum += __shfl_down_sync(0xffffffff, sum, off);
    if (lane == 0) scores[w] = sum + att_b[0];
}

__global__ void segment_kernel(const float* __restrict__ scores,
                               const int* __restrict__ img,
                               const float* __restrict__ ov,
                               float* __restrict__ gvec) {
    int g = blockIdx.x, t = threadIdx.x;   // 128 threads
    __shared__ float sred[128];
    __shared__ int ired[128];

    float m = -3.4e38f;
    int lo = NUM_O, hi = -1;
    for (int i = t; i < NUM_O; i += 128) {
        if (img[i] == g) {
            m = fmaxf(m, scores[i]);
            lo = min(lo, i);
            hi = max(hi, i);
        }
    }
    sred[t] = m; __syncthreads();
    for (int s = 64; s > 0; s >>= 1) { if (t < s) sred[t] = fmaxf(sred[t], sred[t + s]); __syncthreads(); }
    m = sred[0]; __syncthreads();
    ired[t] = lo; __syncthreads();
    for (int s = 64; s > 0; s >>= 1) { if (t < s) ired[t] = min(ired[t], ired[t + s]); __syncthreads(); }
    lo = ired[0]; __syncthreads();
    ired[t] = hi; __syncthreads();
    for (int s = 64; s > 0; s >>= 1) { if (t < s) ired[t] = max(ired[t], ired[t + s]); __syncthreads(); }
    hi = ired[0]; __syncthreads();

    float z = 0.f;
    for (int i = lo + t; i <= hi; i += 128)
        if (img[i] == g) z += expf(scores[i] - m);
    sred[t] = z; __syncthreads();
    for (int s = 64; s > 0; s >>= 1) { if (t < s) sred[t] += sred[t + s]; __syncthreads(); }
    z = sred[0];
    float invz = 1.f / z;

    float acc = 0.f;
    for (int i = lo; i <= hi; i++) {
        if (img[i] == g)
            acc += expf(scores[i] - m) * invz * ov[(size_t)i * DD + t];
    }
    gvec[g * DD + t] = acc;
}

__global__ void concat_kernel(const float* __restrict__ ov,
                              const float* __restrict__ gvec,
                              const int* __restrict__ img,
                              float* __restrict__ out) {
    int i = blockIdx.x, t = threadIdx.x;   // 256 threads
    if (t < DD) out[(size_t)i * 256 + t] = ov[(size_t)i * DD + t];
    else        out[(size_t)i * 256 + t] = gvec[img[i] * DD + (t - DD)];
}

// ================= launch =================
extern "C" void kernel_launch(void* const* d_in, const int* in_sizes, int n_in,
                              void* d_out, int out_size) {
    const int*   objs     = (const int*)d_in[0];
    const int*   trip     = (const int*)d_in[1];
    const int*   img      = (const int*)d_in[2];
    const float* obj_emb  = (const float*)d_in[3];
    const float* pred_emb = (const float*)d_in[4];
    const float* n1w1     = (const float*)d_in[5];
    const float* n1b1     = (const float*)d_in[6];
    const float* n1w2     = (const float*)d_in[7];
    const float* n1b2     = (const float*)d_in[8];
    const float* n2w1     = (const float*)d_in[9];
    const float* n2b1     = (const float*)d_in[10];
    const float* n2w2     = (const float*)d_in[11];
    const float* n2b2     = (const float*)d_in[12];
    const float* att_w    = (const float*)d_in[13];
    const float* att_b    = (const float*)d_in[14];
    float* out = (float*)d_out;

    float *ov, *pooled, *counts, *inv, *scores, *gvec;
    bf16 *ovh, *ovl, *pvh, *pvl, *hh, *hl, *ph, *pl, *h2h, *h2l;
    bf16 *w1h, *w1l, *w2h, *w2l, *w3h, *w3l, *w4h, *w4l;
    cudaGetSymbolAddress((void**)&ov,     g_ov);
    cudaGetSymbolAddress((void**)&pooled, g_pooled);
    cudaGetSymbolAddress((void**)&counts, g_counts);
    cudaGetSymbolAddress((void**)&inv,    g_invcnt);
    cudaGetSymbolAddress((void**)&scores, g_scores);
    cudaGetSymbolAddress((void**)&gvec,   g_gvec);
    cudaGetSymbolAddress((void**)&ovh, g_ovh); cudaGetSymbolAddress((void**)&ovl, g_ovl);
    cudaGetSymbolAddress((void**)&pvh, g_pvh); cudaGetSymbolAddress((void**)&pvl, g_pvl);
    cudaGetSymbolAddress((void**)&hh,  g_hh);  cudaGetSymbolAddress((void**)&hl,  g_hl);
    cudaGetSymbolAddress((void**)&ph,  g_ph);  cudaGetSymbolAddress((void**)&pl,  g_pl);
    cudaGetSymbolAddress((void**)&h2h, g_h2h); cudaGetSymbolAddress((void**)&h2l, g_h2l);
    cudaGetSymbolAddress((void**)&w1h, g_w1h); cudaGetSymbolAddress((void**)&w1l, g_w1l);
    cudaGetSymbolAddress((void**)&w2h, g_w2h); cudaGetSymbolAddress((void**)&w2l, g_w2l);
    cudaGetSymbolAddress((void**)&w3h, g_w3h); cudaGetSymbolAddress((void**)&w3l, g_w3l);
    cudaGetSymbolAddress((void**)&w4h, g_w4h); cudaGetSymbolAddress((void**)&w4l, g_w4l);

    cudaFuncSetAttribute(gemm_hmma<1,1>, cudaFuncAttributeMaxDynamicSharedMemorySize, SMEM_DYN);
    cudaFuncSetAttribute(gemm_hmma<0,3>, cudaFuncAttributeMaxDynamicSharedMemorySize, SMEM_DYN);
    cudaFuncSetAttribute(gemm_hmma<0,1>, cudaFuncAttributeMaxDynamicSharedMemorySize, SMEM_DYN);
    cudaFuncSetAttribute(gemm_hmma<0,2>, cudaFuncAttributeMaxDynamicSharedMemorySize, SMEM_DYN);

    // weight preprocessing
    wtrans_split<<<dim3(HH/32, K1/32, LL), dim3(32,32)>>>(n1w1, w1h, w1l, K1, HH);
    wtrans_split<<<dim3(N2/32, HH/32, LL), dim3(32,32)>>>(n1w2, w2h, w2l, HH, N2);
    wtrans_split<<<dim3(HH/32, HH/32, LL), dim3(32,32)>>>(n2w1, w3h, w3l, HH, HH);
    wtrans_split<<<dim3(DD/32, HH/32, LL), dim3(32,32)>>>(n2w2, w4h, w4l, HH, DD);

    gather_ov_init<<<NUM_O, DD>>>(obj_emb, objs, ovh, ovl);
    gather_pv0<<<NUM_T, DD>>>(pred_emb, trip, pvh, pvl);
    zero_kernel<<<(NUM_O + 255) / 256, 256>>>(counts, NUM_O);
    count_kernel<<<(NUM_T + 255) / 256, 256>>>(trip, counts);
    inv_kernel<<<(NUM_O + 255) / 256, 256>>>(counts, inv);

    const int mT = (NUM_T + BM - 1) / BM;   // 157
    const int mO = (NUM_O + BM - 1) / BM;   // 40

    for (int l = 0; l < LL; l++) {
        // GEMM1: h = relu(gather(ov,pv) @ w1 + b1), out bf16 pair [20000,512,K=384]
        gemm_hmma<1,1><<<dim3(HH/BN, mT), 256, SMEM_DYN>>>(
            nullptr, nullptr, ovh, ovl, pvh, pvl, trip,
            w1h + (size_t)l*HH*K1, w1l + (size_t)l*HH*K1, n1b1 + (size_t)l*HH,
            nullptr, hh, hl, nullptr, nullptr, nullptr, NUM_T, HH, K1);

        zero_kernel<<<(NUM_O * HH + 255) / 256, 256>>>(pooled, NUM_O * HH);

        // GEMM2: fused scatter epilogue [20000,1152,K=512]
        gemm_hmma<0,3><<<dim3(N2/BN, mT), 256, SMEM_DYN>>>(
            hh, hl, nullptr, nullptr, nullptr, nullptr, trip,
            w2h + (size_t)l*N2*HH, w2l + (size_t)l*N2*HH, n1b2 + (size_t)l*N2,
            nullptr, nullptr, nullptr, pooled, pvh, pvl, NUM_T, N2, HH);

        scale_split<<<(NUM_O * HH + 255) / 256, 256>>>(pooled, inv, ph, pl, NUM_O * HH);

        // GEMM3: h2 = relu(pooled @ w3 + b3), out bf16 pair [5000,512,K=512]
        gemm_hmma<0,1><<<dim3(HH/BN, mO), 256, SMEM_DYN>>>(
            ph, pl, nullptr, nullptr, nullptr, nullptr, trip,
            w3h + (size_t)l*HH*HH, w3l + (size_t)l*HH*HH, n2b1 + (size_t)l*HH,
            nullptr, h2h, h2l, nullptr, nullptr, nullptr, NUM_O, HH, HH);

        // GEMM4: ov = relu(h2 @ w4 + b4), out fp32 + bf16 pair [5000,128,K=512]
        gemm_hmma<0,2><<<dim3(DD/BN, mO), 256, SMEM_DYN>>>(
            h2h, h2l, nullptr, nullptr, nullptr, nullptr, trip,
            w4h + (size_t)l*DD*HH, w4l + (size_t)l*DD*HH, n2b2 + (size_t)l*DD,
            ov, ovh, ovl, nullptr, nullptr, nullptr, NUM_O, DD, HH);
    }

    scores_kernel<<<(NUM_O * 32 + 255) / 256, 256>>>(ov, att_w, att_b, scores);
    segment_kernel<<<GG, 128>>>(scores, img, ov, gvec);
    concat_kernel<<<NUM_O, 256>>>(ov, gvec, img, out);
}